// round 15
// baseline (speedup 1.0000x reference)
#include <cuda_runtime.h>
#include <cuda_fp16.h>
#include <cstdint>
#include <cstddef>

#define NTOK 4096
#define HDIM 1024
#define IDIM 4096
#define NEXP 8

// ------------------------- scratch (static device, no allocs) -------------------------
__device__ __half g_x[(size_t)NTOK * HDIM];
__device__ __half g_w1[(size_t)NEXP * IDIM * HDIM];
__device__ __half g_w2[(size_t)NEXP * HDIM * IDIM];
__device__ __half g_mid[(size_t)NEXP * NTOK * IDIM];     // per-expert gelu output
__device__ float g_probs[NTOK * NEXP];

// ------------------------- PTX helpers -------------------------
__device__ __forceinline__ uint32_t smem_u32(const void* p) {
    uint32_t a;
    asm("{ .reg .u64 t; cvta.to.shared.u64 t, %1; cvt.u32.u64 %0, t; }" : "=r"(a) : "l"(p));
    return a;
}

__device__ __forceinline__ void cp_async16(uint32_t smem, const void* g) {
    asm volatile("cp.async.cg.shared.global [%0], [%1], 16;\n" :: "r"(smem), "l"(g));
}

// swizzle for 128B rows: off = row*128 + (colbyte ^ ((row&7)<<4))
__device__ __forceinline__ uint32_t swz_row(uint32_t row, uint32_t colbyte) {
    return row * 128u + (colbyte ^ ((row & 7u) << 4));
}

__device__ __forceinline__ void ldsm_x4(uint32_t (&r)[4], uint32_t addr) {
    asm volatile("ldmatrix.sync.aligned.m8n8.x4.shared.b16 {%0,%1,%2,%3}, [%4];"
                 : "=r"(r[0]), "=r"(r[1]), "=r"(r[2]), "=r"(r[3]) : "r"(addr));
}

__device__ __forceinline__ void mma16816(float (&d)[4], const uint32_t (&a)[4],
                                         const uint32_t (&b)[2]) {
    asm volatile(
        "mma.sync.aligned.m16n8k16.row.col.f32.f16.f16.f32 "
        "{%0,%1,%2,%3}, {%4,%5,%6,%7}, {%8,%9}, {%0,%1,%2,%3};"
        : "+f"(d[0]), "+f"(d[1]), "+f"(d[2]), "+f"(d[3])
        : "r"(a[0]), "r"(a[1]), "r"(a[2]), "r"(a[3]), "r"(b[0]), "r"(b[1]));
}

// -------- prep kernel: router (blocks < 512) + fp32->fp16 convert + zero-init out --------
__global__ void moe_prep_kernel(const float* __restrict__ hs, const float* __restrict__ Wr,
                                const float* __restrict__ W1, const float* __restrict__ W2,
                                __half* __restrict__ xp, __half* __restrict__ w1p,
                                __half* __restrict__ w2p,
                                float* __restrict__ probs, float* __restrict__ zout) {
    if (blockIdx.x < 512) {
        int warp = threadIdx.x >> 5, lane = threadIdx.x & 31;
        int n = blockIdx.x * 8 + warp;
        const float* x = hs + (size_t)n * HDIM;
        float acc[NEXP];
        #pragma unroll
        for (int e = 0; e < NEXP; ++e) acc[e] = 0.f;
        for (int j = lane; j < HDIM; j += 32) {
            float xv = x[j];
            #pragma unroll
            for (int e = 0; e < NEXP; ++e) acc[e] += xv * Wr[e * HDIM + j];
        }
        #pragma unroll
        for (int off = 16; off; off >>= 1) {
            #pragma unroll
            for (int e = 0; e < NEXP; ++e)
                acc[e] += __shfl_down_sync(0xffffffffu, acc[e], off);
        }
        if (lane == 0) {
            float m = acc[0];
            #pragma unroll
            for (int e = 1; e < NEXP; ++e) m = fmaxf(m, acc[e]);
            float s = 0.f, p[NEXP];
            #pragma unroll
            for (int e = 0; e < NEXP; ++e) { p[e] = expf(acc[e] - m); s += p[e]; }
            float inv = 1.f / s;
            #pragma unroll
            for (int e = 0; e < NEXP; ++e) p[e] *= inv;
            #pragma unroll
            for (int i = 1; i < NEXP; ++i) {
                float key = p[i];
                int j = i - 1;
                while (j >= 0 && p[j] < key) { p[j + 1] = p[j]; --j; }
                p[j + 1] = key;
            }
            #pragma unroll
            for (int e = 0; e < NEXP; ++e) probs[n * NEXP + e] = p[e];
        }
    }

    constexpr size_t n0 = (size_t)NTOK * HDIM / 8;
    constexpr size_t n1 = (size_t)NEXP * IDIM * HDIM / 8;
    constexpr size_t n2 = (size_t)NEXP * HDIM * IDIM / 8;
    constexpr size_t nz4 = (size_t)NTOK * HDIM / 4;
    size_t total = n0 + n1 + n2;
    size_t i = (size_t)blockIdx.x * blockDim.x + threadIdx.x;
    size_t stride = (size_t)gridDim.x * blockDim.x;
    for (size_t z = i; z < nz4; z += stride) {
        ((float4*)zout)[z] = make_float4(0.f, 0.f, 0.f, 0.f);
    }
    for (; i < total; i += stride) {
        const float* src;
        __half* dst;
        size_t j = i;
        if (j < n0) { src = hs; dst = xp; }
        else if (j < n0 + n1) { j -= n0; src = W1; dst = w1p; }
        else { j -= n0 + n1; src = W2; dst = w2p; }
        const float4* s = (const float4*)(src + j * 8);
        float4 a = s[0], b = s[1];
        union { __half h[8]; uint4 u; } H;
        H.h[0] = __float2half_rn(a.x); H.h[1] = __float2half_rn(a.y);
        H.h[2] = __float2half_rn(a.z); H.h[3] = __float2half_rn(a.w);
        H.h[4] = __float2half_rn(b.x); H.h[5] = __float2half_rn(b.y);
        H.h[6] = __float2half_rn(b.z); H.h[7] = __float2half_rn(b.w);
        *(uint4*)(dst + j * 8) = H.u;
    }
}

// ------------------------- fp16 GEMM, 128x128 tile, 4 warps of 64x64 ---------------------
// 128 threads, 3-stage cp.async, 1 sync/chunk, interleaved prefetch, 2 CTA/SM, PDL.
// MODE 0: K=HDIM; each CTA processes TWO experts (2*ez, 2*ez+1) back-to-back with a
//         CONTINUOUS pipeline (chunk loop runs 2*NC; A=x is expert-invariant, only the
//         B pointer switches at the boundary; expert-0 epilogue fires mid-loop).
// MODE 1: K=IDIM;  A=mid[z], B=w2[z];  out += prob[m,z] * D  via atomicAdd (REDG)
template <int MODE>
__global__ void __launch_bounds__(128, 2) moe_gemm(float* __restrict__ outp) {
    constexpr int K = (MODE == 0) ? HDIM : IDIM;
    constexpr int MT = 128;
    constexpr int NT = 128;
    constexpr int A_BYTES = MT * 128;          // 16384
    constexpr int B_BYTES = NT * 128;          // 16384
    constexpr int STAGE = A_BYTES + B_BYTES;   // 32768
    constexpr int NSTG = 3;
    constexpr int NC = K / 64;
    constexpr int NCTOT = (MODE == 0) ? 2 * NC : NC;

    extern __shared__ char dsm[];

    const int tid = threadIdx.x, wid = tid >> 5, lane = tid & 31;
    const int m0 = blockIdx.x * MT;
    const int n0 = blockIdx.y * NT;
    const int ez = blockIdx.z;

    const __half* A;
    const __half* B0;
    const __half* B1;
    if (MODE == 0) {
        A = g_x;
        B0 = g_w1 + (size_t)(2 * ez) * IDIM * HDIM;
        B1 = B0 + (size_t)IDIM * HDIM;
    } else {
        A = g_mid + (size_t)ez * NTOK * IDIM;
        B0 = g_w2 + (size_t)ez * HDIM * IDIM;
        B1 = B0;
    }

    uint32_t tiles = (smem_u32(dsm) + 1023u) & ~1023u;

    // chunk c -> (k-offset, B pointer)
    auto chunk_src = [&](int c, int& kk, const __half*& Bp) {
        if (MODE == 0 && c >= NC) { kk = (c - NC) * 64; Bp = B1; }
        else                      { kk = c * 64;        Bp = B0; }
    };

    auto load_chunk = [&](int c, int b) {
        int kk; const __half* Bp;
        chunk_src(c, kk, Bp);
        uint32_t sA = tiles + b * STAGE;
        uint32_t sB = sA + A_BYTES;
        #pragma unroll
        for (int v = 0; v < 8; ++v) {
            int idx = v * 128 + tid;
            int r = idx >> 3, c16 = idx & 7;
            cp_async16(sA + swz_row((uint32_t)r, (uint32_t)(c16 * 16)),
                       A + (size_t)(m0 + r) * K + kk + c16 * 8);
        }
        #pragma unroll
        for (int v = 0; v < 8; ++v) {
            int idx = v * 128 + tid;
            int r = idx >> 3, c16 = idx & 7;
            cp_async16(sB + swz_row((uint32_t)r, (uint32_t)(c16 * 16)),
                       Bp + (size_t)(n0 + r) * K + kk + c16 * 8);
        }
        asm volatile("cp.async.commit_group;\n" ::: "memory");
    };

    // Quarter-chunk load: part p issues 2 A-vecs and 2 B-vecs.
    auto load_part = [&](int c, int b, int p) {
        int kk; const __half* Bp;
        chunk_src(c, kk, Bp);
        uint32_t sA = tiles + b * STAGE;
        uint32_t sB = sA + A_BYTES;
        #pragma unroll
        for (int v = 0; v < 2; ++v) {
            int idx = (2 * p + v) * 128 + tid;
            int r = idx >> 3, c16 = idx & 7;
            cp_async16(sA + swz_row((uint32_t)r, (uint32_t)(c16 * 16)),
                       A + (size_t)(m0 + r) * K + kk + c16 * 8);
        }
        #pragma unroll
        for (int v = 0; v < 2; ++v) {
            int idx = (2 * p + v) * 128 + tid;
            int r = idx >> 3, c16 = idx & 7;
            cp_async16(sB + swz_row((uint32_t)r, (uint32_t)(c16 * 16)),
                       Bp + (size_t)(n0 + r) * K + kk + c16 * 8);
        }
    };

    const int wm = (wid & 1) * 64;
    const int wn = (wid >> 1) * 64;

    float acc[4][8][4];
    #pragma unroll
    for (int mt = 0; mt < 4; ++mt)
        #pragma unroll
        for (int nt = 0; nt < 8; ++nt)
            #pragma unroll
            for (int q = 0; q < 4; ++q) acc[mt][nt][q] = 0.f;

    const uint32_t rA = (((uint32_t)lane >> 3) & 1u) * 8u + ((uint32_t)lane & 7u);
    const uint32_t kA0 = (((uint32_t)lane >> 4) & 1u) * 16u;
    const uint32_t rB = (((uint32_t)lane >> 4) & 1u) * 8u + ((uint32_t)lane & 7u);
    const uint32_t kB0 = (((uint32_t)lane >> 3) & 1u) * 16u;

    const int rbase = m0 + wm + (lane >> 2);
    const int cbase = n0 + wn + (lane & 3) * 2;

    // MODE 0 epilogue for expert slot esel (0 or 1); registers only, no smem/barrier.
    auto mid_epilogue = [&](int esel) {
        __half* mid = g_mid + (size_t)(2 * ez + esel) * NTOK * IDIM;
        #pragma unroll
        for (int mt = 0; mt < 4; ++mt) {
            #pragma unroll
            for (int half = 0; half < 2; ++half) {
                int row = rbase + mt * 16 + half * 8;
                size_t base = (size_t)row * IDIM;
                #pragma unroll
                for (int nt = 0; nt < 8; ++nt) {
                    int col = cbase + nt * 8;
                    float v0 = acc[mt][nt][half * 2 + 0];
                    float v1 = acc[mt][nt][half * 2 + 1];
                    float g0 = 0.5f * v0 * (1.0f + erff(v0 * 0.70710678118654752f));
                    float g1 = 0.5f * v1 * (1.0f + erff(v1 * 0.70710678118654752f));
                    __half2 h2;
                    h2.x = __float2half_rn(g0);
                    h2.y = __float2half_rn(g1);
                    *(__half2*)(mid + base + col) = h2;
                }
            }
        }
    };

    // PDL: wait for producer kernel's data before first dependent global read.
    cudaGridDependencySynchronize();

    load_chunk(0, 0);
    load_chunk(1, 1);

    for (int c = 0; c < NCTOT; ++c) {
        int b = c % NSTG;
        if (c + 1 < NCTOT) asm volatile("cp.async.wait_group 1;\n" ::: "memory");
        else               asm volatile("cp.async.wait_group 0;\n" ::: "memory");
        __syncthreads();

        const bool pf = (c + 2 < NCTOT);
        const int pb = (c + 2) % NSTG;

        uint32_t sA = tiles + b * STAGE;
        uint32_t sB = sA + A_BYTES;

        #pragma unroll
        for (int ks = 0; ks < 4; ++ks) {
            uint32_t af[4][4];
            #pragma unroll
            for (int mt = 0; mt < 4; ++mt) {
                uint32_t row = (uint32_t)(wm + mt * 16) + rA;
                ldsm_x4(af[mt], sA + swz_row(row, (uint32_t)(ks * 32) + kA0));
            }
            uint32_t bfr[8][2];
            #pragma unroll
            for (int nt2 = 0; nt2 < 4; ++nt2) {
                uint32_t t[4];
                uint32_t row = (uint32_t)(wn + nt2 * 16) + rB;
                ldsm_x4(t, sB + swz_row(row, (uint32_t)(ks * 32) + kB0));
                bfr[2 * nt2][0] = t[0]; bfr[2 * nt2][1] = t[1];
                bfr[2 * nt2 + 1][0] = t[2]; bfr[2 * nt2 + 1][1] = t[3];
            }
            if (pf) load_part(c + 2, pb, ks);
            #pragma unroll
            for (int mt = 0; mt < 4; ++mt)
                #pragma unroll
                for (int nt = 0; nt < 8; ++nt)
                    mma16816(acc[mt][nt], af[mt], bfr[nt]);
        }
        if (pf) asm volatile("cp.async.commit_group;\n" ::: "memory");

        // MODE 0: expert-0 finishes at c == NC-1; store its tile and reset acc while
        // the pipeline keeps streaming expert-1's chunks.
        if (MODE == 0 && c == NC - 1) {
            mid_epilogue(0);
            #pragma unroll
            for (int mt = 0; mt < 4; ++mt)
                #pragma unroll
                for (int nt = 0; nt < 8; ++nt)
                    #pragma unroll
                    for (int q = 0; q < 4; ++q) acc[mt][nt][q] = 0.f;
        }
    }

    // ------------------------- final epilogue -------------------------
    if (MODE == 0) {
        mid_epilogue(1);
        __threadfence();
        cudaTriggerProgrammaticLaunchCompletion();
    } else {
        #pragma unroll
        for (int mt = 0; mt < 4; ++mt) {
            #pragma unroll
            for (int half = 0; half < 2; ++half) {
                int row = rbase + mt * 16 + half * 8;
                float pw = g_probs[row * NEXP + ez];
                size_t base = (size_t)row * HDIM;
                #pragma unroll
                for (int nt = 0; nt < 8; ++nt) {
                    int col = cbase + nt * 8;
                    float* o = outp + base + col;
                    atomicAdd(o + 0, acc[mt][nt][half * 2 + 0] * pw);
                    atomicAdd(o + 1, acc[mt][nt][half * 2 + 1] * pw);
                }
            }
        }
    }
}

// ------------------------- host launch -------------------------
extern "C" void kernel_launch(void* const* d_in, const int* in_sizes, int n_in,
                              void* d_out, int out_size) {
    const float* hs = (const float*)d_in[0];
    const float* Wr = (const float*)d_in[1];
    const float* W1 = (const float*)d_in[2];
    const float* W2 = (const float*)d_in[3];
    float* outp = (float*)d_out;

    void *xp, *w1p, *w2p, *pp;
    cudaGetSymbolAddress(&xp, g_x);
    cudaGetSymbolAddress(&w1p, g_w1);
    cudaGetSymbolAddress(&w2p, g_w2);
    cudaGetSymbolAddress(&pp, g_probs);

    const int SMEM = 1024 + 3 * 32768;   // 99328/CTA, 2 CTA/SM
    cudaFuncSetAttribute((const void*)moe_gemm<0>,
                         cudaFuncAttributeMaxDynamicSharedMemorySize, SMEM);
    cudaFuncSetAttribute((const void*)moe_gemm<1>,
                         cudaFuncAttributeMaxDynamicSharedMemorySize, SMEM);

    // prep: router + converts + zero-init (one launch)
    moe_prep_kernel<<<5120, 256>>>(hs, Wr, W1, W2,
                                   (__half*)xp, (__half*)w1p, (__half*)w2p,
                                   (float*)pp, outp);

    cudaLaunchAttribute attrs[1];
    attrs[0].id = cudaLaunchAttributeProgrammaticStreamSerialization;
    attrs[0].val.programmaticStreamSerializationAllowed = 1;

    // GEMM1: 2 experts per CTA (grid 32x32x4 = 4096 CTAs, continuous pipeline)
    {
        cudaLaunchConfig_t cfg = {};
        cfg.gridDim = dim3(NTOK / 128, IDIM / 128, NEXP / 2);
        cfg.blockDim = dim3(128, 1, 1);
        cfg.dynamicSmemBytes = SMEM;
        cfg.attrs = attrs;
        cfg.numAttrs = 1;
        cudaLaunchKernelEx(&cfg, moe_gemm<0>, (float*)nullptr);
    }
    // GEMM2: all experts (grid 32x8x8 = 2048 CTAs), atomic accumulate into out
    {
        cudaLaunchConfig_t cfg = {};
        cfg.gridDim = dim3(NTOK / 128, HDIM / 128, NEXP);
        cfg.blockDim = dim3(128, 1, 1);
        cfg.dynamicSmemBytes = SMEM;
        cfg.attrs = attrs;
        cfg.numAttrs = 1;
        cudaLaunchKernelEx(&cfg, moe_gemm<1>, outp);
    }
}

// round 16
// speedup vs baseline: 1.0334x; 1.0334x over previous
#include <cuda_runtime.h>
#include <cuda_fp16.h>
#include <cstdint>
#include <cstddef>

#define NTOK 4096
#define HDIM 1024
#define IDIM 4096
#define NEXP 8

// ------------------------- scratch (static device, no allocs) -------------------------
__device__ __half g_x[(size_t)NTOK * HDIM];
__device__ __half g_w1[(size_t)NEXP * IDIM * HDIM];
__device__ __half g_w2[(size_t)NEXP * HDIM * IDIM];
__device__ __half g_mid[(size_t)NEXP * NTOK * IDIM];     // per-expert gelu output
__device__ float g_probs[NTOK * NEXP];

// ------------------------- PTX helpers -------------------------
__device__ __forceinline__ uint32_t smem_u32(const void* p) {
    uint32_t a;
    asm("{ .reg .u64 t; cvta.to.shared.u64 t, %1; cvt.u32.u64 %0, t; }" : "=r"(a) : "l"(p));
    return a;
}

__device__ __forceinline__ void cp_async16(uint32_t smem, const void* g) {
    asm volatile("cp.async.cg.shared.global [%0], [%1], 16;\n" :: "r"(smem), "l"(g));
}

// swizzle for 128B rows: off = row*128 + (colbyte ^ ((row&7)<<4))
__device__ __forceinline__ uint32_t swz_row(uint32_t row, uint32_t colbyte) {
    return row * 128u + (colbyte ^ ((row & 7u) << 4));
}

__device__ __forceinline__ void ldsm_x4(uint32_t (&r)[4], uint32_t addr) {
    asm volatile("ldmatrix.sync.aligned.m8n8.x4.shared.b16 {%0,%1,%2,%3}, [%4];"
                 : "=r"(r[0]), "=r"(r[1]), "=r"(r[2]), "=r"(r[3]) : "r"(addr));
}

__device__ __forceinline__ void mma16816(float (&d)[4], const uint32_t (&a)[4],
                                         const uint32_t (&b)[2]) {
    asm volatile(
        "mma.sync.aligned.m16n8k16.row.col.f32.f16.f16.f32 "
        "{%0,%1,%2,%3}, {%4,%5,%6,%7}, {%8,%9}, {%0,%1,%2,%3};"
        : "+f"(d[0]), "+f"(d[1]), "+f"(d[2]), "+f"(d[3])
        : "r"(a[0]), "r"(a[1]), "r"(a[2]), "r"(a[3]), "r"(b[0]), "r"(b[1]));
}

__device__ __forceinline__ void cvt8(const float* __restrict__ src, __half* __restrict__ dst,
                                     size_t j) {
    const float4* s = (const float4*)(src + j * 8);
    float4 a = s[0], b = s[1];
    union { __half h[8]; uint4 u; } H;
    H.h[0] = __float2half_rn(a.x); H.h[1] = __float2half_rn(a.y);
    H.h[2] = __float2half_rn(a.z); H.h[3] = __float2half_rn(a.w);
    H.h[4] = __float2half_rn(b.x); H.h[5] = __float2half_rn(b.y);
    H.h[6] = __float2half_rn(b.z); H.h[7] = __float2half_rn(b.w);
    *(uint4*)(dst + j * 8) = H.u;
}

// -------- prep1: zero-init out + convert x, W1 (critical path for GEMM1) -----------------
__global__ void moe_prep1_kernel(const float* __restrict__ hs, const float* __restrict__ W1,
                                 __half* __restrict__ xp, __half* __restrict__ w1p,
                                 float* __restrict__ zout) {
    constexpr size_t n0 = (size_t)NTOK * HDIM / 8;
    constexpr size_t n1 = (size_t)NEXP * IDIM * HDIM / 8;
    constexpr size_t nz4 = (size_t)NTOK * HDIM / 4;
    size_t total = n0 + n1;
    size_t i = (size_t)blockIdx.x * blockDim.x + threadIdx.x;
    size_t stride = (size_t)gridDim.x * blockDim.x;
    for (size_t z = i; z < nz4; z += stride) {
        ((float4*)zout)[z] = make_float4(0.f, 0.f, 0.f, 0.f);
    }
    for (; i < total; i += stride) {
        if (i < n0) cvt8(hs, xp, i);
        else        cvt8(W1, w1p, i - n0);
    }
}

// -------- prep2 (side stream): router + convert W2 (needed only by GEMM2) ----------------
__global__ void moe_prep2_kernel(const float* __restrict__ hs, const float* __restrict__ Wr,
                                 const float* __restrict__ W2, __half* __restrict__ w2p,
                                 float* __restrict__ probs) {
    if (blockIdx.x < 512) {
        int warp = threadIdx.x >> 5, lane = threadIdx.x & 31;
        int n = blockIdx.x * 8 + warp;
        const float* x = hs + (size_t)n * HDIM;
        float acc[NEXP];
        #pragma unroll
        for (int e = 0; e < NEXP; ++e) acc[e] = 0.f;
        for (int j = lane; j < HDIM; j += 32) {
            float xv = x[j];
            #pragma unroll
            for (int e = 0; e < NEXP; ++e) acc[e] += xv * Wr[e * HDIM + j];
        }
        #pragma unroll
        for (int off = 16; off; off >>= 1) {
            #pragma unroll
            for (int e = 0; e < NEXP; ++e)
                acc[e] += __shfl_down_sync(0xffffffffu, acc[e], off);
        }
        if (lane == 0) {
            float m = acc[0];
            #pragma unroll
            for (int e = 1; e < NEXP; ++e) m = fmaxf(m, acc[e]);
            float s = 0.f, p[NEXP];
            #pragma unroll
            for (int e = 0; e < NEXP; ++e) { p[e] = expf(acc[e] - m); s += p[e]; }
            float inv = 1.f / s;
            #pragma unroll
            for (int e = 0; e < NEXP; ++e) p[e] *= inv;
            #pragma unroll
            for (int i = 1; i < NEXP; ++i) {
                float key = p[i];
                int j = i - 1;
                while (j >= 0 && p[j] < key) { p[j + 1] = p[j]; --j; }
                p[j + 1] = key;
            }
            #pragma unroll
            for (int e = 0; e < NEXP; ++e) probs[n * NEXP + e] = p[e];
        }
    }
    constexpr size_t n2 = (size_t)NEXP * HDIM * IDIM / 8;
    size_t i = (size_t)blockIdx.x * blockDim.x + threadIdx.x;
    size_t stride = (size_t)gridDim.x * blockDim.x;
    for (; i < n2; i += stride) cvt8(W2, w2p, i);
}

// ------------------------- fp16 GEMM, 128x128 tile, 4 warps of 64x64 ---------------------
// R14 engine: 128 threads, 3-stage cp.async, 1 sync/chunk, interleaved prefetch,
// 2 CTA/SM, PDL between gemm<0> -> gemm<1>.
// MODE 0: K=HDIM;  A=x, B=w1[z];  mid[z] = fp16(gelu(D))
// MODE 1: K=IDIM;  A=mid[z], B=w2[z];  out += prob[m,z] * D  via atomicAdd (REDG)
template <int MODE>
__global__ void __launch_bounds__(128, 2) moe_gemm(float* __restrict__ outp) {
    constexpr int K = (MODE == 0) ? HDIM : IDIM;
    constexpr int MT = 128;
    constexpr int NT = 128;
    constexpr int A_BYTES = MT * 128;          // 16384
    constexpr int B_BYTES = NT * 128;          // 16384
    constexpr int STAGE = A_BYTES + B_BYTES;   // 32768
    constexpr int NSTG = 3;
    constexpr int NC = K / 64;

    extern __shared__ char dsm[];

    const int tid = threadIdx.x, wid = tid >> 5, lane = tid & 31;
    const int m0 = blockIdx.x * MT;
    const int n0 = blockIdx.y * NT;
    const int ez = blockIdx.z;

    const __half* A;
    const __half* B;
    if (MODE == 0) {
        A = g_x;
        B = g_w1 + (size_t)ez * IDIM * HDIM;
    } else {
        A = g_mid + (size_t)ez * NTOK * IDIM;
        B = g_w2 + (size_t)ez * HDIM * IDIM;
    }

    uint32_t tiles = (smem_u32(dsm) + 1023u) & ~1023u;

    auto load_chunk = [&](int c, int b) {
        int kk = c * 64;
        uint32_t sA = tiles + b * STAGE;
        uint32_t sB = sA + A_BYTES;
        #pragma unroll
        for (int v = 0; v < 8; ++v) {
            int idx = v * 128 + tid;
            int r = idx >> 3, c16 = idx & 7;
            cp_async16(sA + swz_row((uint32_t)r, (uint32_t)(c16 * 16)),
                       A + (size_t)(m0 + r) * K + kk + c16 * 8);
        }
        #pragma unroll
        for (int v = 0; v < 8; ++v) {
            int idx = v * 128 + tid;
            int r = idx >> 3, c16 = idx & 7;
            cp_async16(sB + swz_row((uint32_t)r, (uint32_t)(c16 * 16)),
                       B + (size_t)(n0 + r) * K + kk + c16 * 8);
        }
        asm volatile("cp.async.commit_group;\n" ::: "memory");
    };

    auto load_part = [&](int c, int b, int p) {
        int kk = c * 64;
        uint32_t sA = tiles + b * STAGE;
        uint32_t sB = sA + A_BYTES;
        #pragma unroll
        for (int v = 0; v < 2; ++v) {
            int idx = (2 * p + v) * 128 + tid;
            int r = idx >> 3, c16 = idx & 7;
            cp_async16(sA + swz_row((uint32_t)r, (uint32_t)(c16 * 16)),
                       A + (size_t)(m0 + r) * K + kk + c16 * 8);
        }
        #pragma unroll
        for (int v = 0; v < 2; ++v) {
            int idx = (2 * p + v) * 128 + tid;
            int r = idx >> 3, c16 = idx & 7;
            cp_async16(sB + swz_row((uint32_t)r, (uint32_t)(c16 * 16)),
                       B + (size_t)(n0 + r) * K + kk + c16 * 8);
        }
    };

    const int wm = (wid & 1) * 64;
    const int wn = (wid >> 1) * 64;

    float acc[4][8][4];
    #pragma unroll
    for (int mt = 0; mt < 4; ++mt)
        #pragma unroll
        for (int nt = 0; nt < 8; ++nt)
            #pragma unroll
            for (int q = 0; q < 4; ++q) acc[mt][nt][q] = 0.f;

    const uint32_t rA = (((uint32_t)lane >> 3) & 1u) * 8u + ((uint32_t)lane & 7u);
    const uint32_t kA0 = (((uint32_t)lane >> 4) & 1u) * 16u;
    const uint32_t rB = (((uint32_t)lane >> 4) & 1u) * 8u + ((uint32_t)lane & 7u);
    const uint32_t kB0 = (((uint32_t)lane >> 3) & 1u) * 16u;

    // PDL: wait for producer kernel's data before the first dependent global read.
    cudaGridDependencySynchronize();

    load_chunk(0, 0);
    load_chunk(1, 1);

    for (int c = 0; c < NC; ++c) {
        int b = c % NSTG;
        if (c + 1 < NC) asm volatile("cp.async.wait_group 1;\n" ::: "memory");
        else            asm volatile("cp.async.wait_group 0;\n" ::: "memory");
        __syncthreads();

        const bool pf = (c + 2 < NC);
        const int pb = (c + 2) % NSTG;

        uint32_t sA = tiles + b * STAGE;
        uint32_t sB = sA + A_BYTES;

        #pragma unroll
        for (int ks = 0; ks < 4; ++ks) {
            uint32_t af[4][4];
            #pragma unroll
            for (int mt = 0; mt < 4; ++mt) {
                uint32_t row = (uint32_t)(wm + mt * 16) + rA;
                ldsm_x4(af[mt], sA + swz_row(row, (uint32_t)(ks * 32) + kA0));
            }
            uint32_t bfr[8][2];
            #pragma unroll
            for (int nt2 = 0; nt2 < 4; ++nt2) {
                uint32_t t[4];
                uint32_t row = (uint32_t)(wn + nt2 * 16) + rB;
                ldsm_x4(t, sB + swz_row(row, (uint32_t)(ks * 32) + kB0));
                bfr[2 * nt2][0] = t[0]; bfr[2 * nt2][1] = t[1];
                bfr[2 * nt2 + 1][0] = t[2]; bfr[2 * nt2 + 1][1] = t[3];
            }
            if (pf) load_part(c + 2, pb, ks);
            #pragma unroll
            for (int mt = 0; mt < 4; ++mt)
                #pragma unroll
                for (int nt = 0; nt < 8; ++nt)
                    mma16816(acc[mt][nt], af[mt], bfr[nt]);
        }
        if (pf) asm volatile("cp.async.commit_group;\n" ::: "memory");
    }

    // ------------------------- epilogue -------------------------
    const int rbase = m0 + wm + (lane >> 2);
    const int cbase = n0 + wn + (lane & 3) * 2;

    if (MODE == 0) {
        __half* mid = g_mid + (size_t)ez * NTOK * IDIM;
        #pragma unroll
        for (int mt = 0; mt < 4; ++mt) {
            #pragma unroll
            for (int half = 0; half < 2; ++half) {
                int row = rbase + mt * 16 + half * 8;
                size_t base = (size_t)row * IDIM;
                #pragma unroll
                for (int nt = 0; nt < 8; ++nt) {
                    int col = cbase + nt * 8;
                    float v0 = acc[mt][nt][half * 2 + 0];
                    float v1 = acc[mt][nt][half * 2 + 1];
                    float g0 = 0.5f * v0 * (1.0f + erff(v0 * 0.70710678118654752f));
                    float g1 = 0.5f * v1 * (1.0f + erff(v1 * 0.70710678118654752f));
                    __half2 h2;
                    h2.x = __float2half_rn(g0);
                    h2.y = __float2half_rn(g1);
                    *(__half2*)(mid + base + col) = h2;
                }
            }
        }
        __threadfence();
        cudaTriggerProgrammaticLaunchCompletion();
    } else {
        #pragma unroll
        for (int mt = 0; mt < 4; ++mt) {
            #pragma unroll
            for (int half = 0; half < 2; ++half) {
                int row = rbase + mt * 16 + half * 8;
                float pw = g_probs[row * NEXP + ez];
                size_t base = (size_t)row * HDIM;
                #pragma unroll
                for (int nt = 0; nt < 8; ++nt) {
                    int col = cbase + nt * 8;
                    float* o = outp + base + col;
                    atomicAdd(o + 0, acc[mt][nt][half * 2 + 0] * pw);
                    atomicAdd(o + 1, acc[mt][nt][half * 2 + 1] * pw);
                }
            }
        }
    }
}

// ------------------------- host launch -------------------------
extern "C" void kernel_launch(void* const* d_in, const int* in_sizes, int n_in,
                              void* d_out, int out_size) {
    const float* hs = (const float*)d_in[0];
    const float* Wr = (const float*)d_in[1];
    const float* W1 = (const float*)d_in[2];
    const float* W2 = (const float*)d_in[3];
    float* outp = (float*)d_out;

    void *xp, *w1p, *w2p, *pp;
    cudaGetSymbolAddress(&xp, g_x);
    cudaGetSymbolAddress(&w1p, g_w1);
    cudaGetSymbolAddress(&w2p, g_w2);
    cudaGetSymbolAddress(&pp, g_probs);

    const int SMEM = 1024 + 3 * 32768;   // 99328/CTA, 2 CTA/SM
    cudaFuncSetAttribute((const void*)moe_gemm<0>,
                         cudaFuncAttributeMaxDynamicSharedMemorySize, SMEM);
    cudaFuncSetAttribute((const void*)moe_gemm<1>,
                         cudaFuncAttributeMaxDynamicSharedMemorySize, SMEM);

    // Stream/event resources: created once on the first (uncaptured) correctness
    // call; only reused (as graph fork/join edges) during capture.
    static cudaStream_t s_side = nullptr;
    static cudaEvent_t ev_fork = nullptr, ev_prep2 = nullptr;
    if (!s_side) {
        cudaStreamCreateWithFlags(&s_side, cudaStreamNonBlocking);
        cudaEventCreateWithFlags(&ev_fork, cudaEventDisableTiming);
        cudaEventCreateWithFlags(&ev_prep2, cudaEventDisableTiming);
    }

    // Fork side stream from main stream.
    cudaEventRecord(ev_fork, 0);
    cudaStreamWaitEvent(s_side, ev_fork, 0);

    // Side stream: router + W2 conversion (only needed by GEMM2) — hides under GEMM1.
    moe_prep2_kernel<<<4096, 256, 0, s_side>>>(hs, Wr, W2, (__half*)w2p, (float*)pp);
    cudaEventRecord(ev_prep2, s_side);

    // Main stream: minimal critical-path prep (zero-init + x, W1 conversion).
    moe_prep1_kernel<<<4096, 256>>>(hs, W1, (__half*)xp, (__half*)w1p, outp);

    cudaLaunchAttribute attrs[1];
    attrs[0].id = cudaLaunchAttributeProgrammaticStreamSerialization;
    attrs[0].val.programmaticStreamSerializationAllowed = 1;

    // GEMM1: all experts (grid 32x32x8 = 8192 CTAs, 27.7 waves at 2 CTA/SM)
    {
        cudaLaunchConfig_t cfg = {};
        cfg.gridDim = dim3(NTOK / 128, IDIM / 128, NEXP);
        cfg.blockDim = dim3(128, 1, 1);
        cfg.dynamicSmemBytes = SMEM;
        cfg.attrs = attrs;
        cfg.numAttrs = 1;
        cudaLaunchKernelEx(&cfg, moe_gemm<0>, (float*)nullptr);
    }

    // Join: GEMM2 needs probs + w2 (side stream) and mid (main stream order).
    cudaStreamWaitEvent(0, ev_prep2, 0);

    // GEMM2: all experts (grid 32x8x8 = 2048 CTAs), atomic accumulate into out
    {
        cudaLaunchConfig_t cfg = {};
        cfg.gridDim = dim3(NTOK / 128, HDIM / 128, NEXP);
        cfg.blockDim = dim3(128, 1, 1);
        cfg.dynamicSmemBytes = SMEM;
        cfg.attrs = attrs;
        cfg.numAttrs = 1;
        cudaLaunchKernelEx(&cfg, moe_gemm<1>, outp);
    }
}

// round 17
// speedup vs baseline: 1.0391x; 1.0055x over previous
#include <cuda_runtime.h>
#include <cuda_fp16.h>
#include <cstdint>
#include <cstddef>

#define NTOK 4096
#define HDIM 1024
#define IDIM 4096
#define NEXP 8

// ------------------------- scratch (static device, no allocs) -------------------------
__device__ __half g_x[(size_t)NTOK * HDIM];
__device__ __half g_w1[(size_t)NEXP * IDIM * HDIM];
__device__ __half g_w2[(size_t)NEXP * HDIM * IDIM];
__device__ __half g_mid[(size_t)NEXP * NTOK * IDIM];     // per-expert gelu output
__device__ float g_probs[NTOK * NEXP];

// ------------------------- PTX helpers -------------------------
__device__ __forceinline__ uint32_t smem_u32(const void* p) {
    uint32_t a;
    asm("{ .reg .u64 t; cvta.to.shared.u64 t, %1; cvt.u32.u64 %0, t; }" : "=r"(a) : "l"(p));
    return a;
}

__device__ __forceinline__ void cp_async16(uint32_t smem, const void* g) {
    asm volatile("cp.async.cg.shared.global [%0], [%1], 16;\n" :: "r"(smem), "l"(g));
}

// swizzle for 128B rows: off = row*128 + (colbyte ^ ((row&7)<<4))
__device__ __forceinline__ uint32_t swz_row(uint32_t row, uint32_t colbyte) {
    return row * 128u + (colbyte ^ ((row & 7u) << 4));
}

__device__ __forceinline__ void ldsm_x4(uint32_t (&r)[4], uint32_t addr) {
    asm volatile("ldmatrix.sync.aligned.m8n8.x4.shared.b16 {%0,%1,%2,%3}, [%4];"
                 : "=r"(r[0]), "=r"(r[1]), "=r"(r[2]), "=r"(r[3]) : "r"(addr));
}

__device__ __forceinline__ void mma16816(float (&d)[4], const uint32_t (&a)[4],
                                         const uint32_t (&b)[2]) {
    asm volatile(
        "mma.sync.aligned.m16n8k16.row.col.f32.f16.f16.f32 "
        "{%0,%1,%2,%3}, {%4,%5,%6,%7}, {%8,%9}, {%0,%1,%2,%3};"
        : "+f"(d[0]), "+f"(d[1]), "+f"(d[2]), "+f"(d[3])
        : "r"(a[0]), "r"(a[1]), "r"(a[2]), "r"(a[3]), "r"(b[0]), "r"(b[1]));
}

__device__ __forceinline__ void cvt8(const float* __restrict__ src, __half* __restrict__ dst,
                                     size_t j) {
    const float4* s = (const float4*)(src + j * 8);
    float4 a = s[0], b = s[1];
    union { __half h[8]; uint4 u; } H;
    H.h[0] = __float2half_rn(a.x); H.h[1] = __float2half_rn(a.y);
    H.h[2] = __float2half_rn(a.z); H.h[3] = __float2half_rn(a.w);
    H.h[4] = __float2half_rn(b.x); H.h[5] = __float2half_rn(b.y);
    H.h[6] = __float2half_rn(b.z); H.h[7] = __float2half_rn(b.w);
    *(uint4*)(dst + j * 8) = H.u;
}

// -------- prep1: zero-init out + convert x, W1 (critical path for GEMM1) -----------------
__global__ void moe_prep1_kernel(const float* __restrict__ hs, const float* __restrict__ W1,
                                 __half* __restrict__ xp, __half* __restrict__ w1p,
                                 float* __restrict__ zout) {
    constexpr size_t n0 = (size_t)NTOK * HDIM / 8;
    constexpr size_t n1 = (size_t)NEXP * IDIM * HDIM / 8;
    constexpr size_t nz4 = (size_t)NTOK * HDIM / 4;
    size_t total = n0 + n1;
    size_t i = (size_t)blockIdx.x * blockDim.x + threadIdx.x;
    size_t stride = (size_t)gridDim.x * blockDim.x;
    for (size_t z = i; z < nz4; z += stride) {
        ((float4*)zout)[z] = make_float4(0.f, 0.f, 0.f, 0.f);
    }
    for (; i < total; i += stride) {
        if (i < n0) cvt8(hs, xp, i);
        else        cvt8(W1, w1p, i - n0);
    }
}

// -------- prep2 (side stream, concurrent with GEMM1): router + convert W2 ----------------
__global__ void moe_prep2_kernel(const float* __restrict__ hs, const float* __restrict__ Wr,
                                 const float* __restrict__ W2, __half* __restrict__ w2p,
                                 float* __restrict__ probs) {
    if (blockIdx.x < 512) {
        int warp = threadIdx.x >> 5, lane = threadIdx.x & 31;
        int n = blockIdx.x * 8 + warp;
        const float* x = hs + (size_t)n * HDIM;
        float acc[NEXP];
        #pragma unroll
        for (int e = 0; e < NEXP; ++e) acc[e] = 0.f;
        for (int j = lane; j < HDIM; j += 32) {
            float xv = x[j];
            #pragma unroll
            for (int e = 0; e < NEXP; ++e) acc[e] += xv * Wr[e * HDIM + j];
        }
        #pragma unroll
        for (int off = 16; off; off >>= 1) {
            #pragma unroll
            for (int e = 0; e < NEXP; ++e)
                acc[e] += __shfl_down_sync(0xffffffffu, acc[e], off);
        }
        if (lane == 0) {
            float m = acc[0];
            #pragma unroll
            for (int e = 1; e < NEXP; ++e) m = fmaxf(m, acc[e]);
            float s = 0.f, p[NEXP];
            #pragma unroll
            for (int e = 0; e < NEXP; ++e) { p[e] = expf(acc[e] - m); s += p[e]; }
            float inv = 1.f / s;
            #pragma unroll
            for (int e = 0; e < NEXP; ++e) p[e] *= inv;
            #pragma unroll
            for (int i = 1; i < NEXP; ++i) {
                float key = p[i];
                int j = i - 1;
                while (j >= 0 && p[j] < key) { p[j + 1] = p[j]; --j; }
                p[j + 1] = key;
            }
            #pragma unroll
            for (int e = 0; e < NEXP; ++e) probs[n * NEXP + e] = p[e];
        }
    }
    constexpr size_t n2 = (size_t)NEXP * HDIM * IDIM / 8;
    size_t i = (size_t)blockIdx.x * blockDim.x + threadIdx.x;
    size_t stride = (size_t)gridDim.x * blockDim.x;
    for (; i < n2; i += stride) cvt8(W2, w2p, i);
}

// ------------------------- fp16 GEMM, 128x128 tile, 4 warps of 64x64 ---------------------
// R14 engine: 128 threads, 3-stage cp.async, 1 sync/chunk, interleaved prefetch,
// 2 CTA/SM, PDL between producer -> consumer on the main stream.
// MODE 0: K=HDIM;  A=x, B=w1[z];  mid[z] = fp16(gelu(D))
// MODE 1: K=IDIM;  A=mid[z], B=w2[z];  out += prob[m,z] * D  via atomicAdd (REDG)
template <int MODE>
__global__ void __launch_bounds__(128, 2) moe_gemm(float* __restrict__ outp) {
    constexpr int K = (MODE == 0) ? HDIM : IDIM;
    constexpr int MT = 128;
    constexpr int NT = 128;
    constexpr int A_BYTES = MT * 128;          // 16384
    constexpr int B_BYTES = NT * 128;          // 16384
    constexpr int STAGE = A_BYTES + B_BYTES;   // 32768
    constexpr int NSTG = 3;
    constexpr int NC = K / 64;

    extern __shared__ char dsm[];

    const int tid = threadIdx.x, wid = tid >> 5, lane = tid & 31;
    const int m0 = blockIdx.x * MT;
    const int n0 = blockIdx.y * NT;
    const int ez = blockIdx.z;

    const __half* A;
    const __half* B;
    if (MODE == 0) {
        A = g_x;
        B = g_w1 + (size_t)ez * IDIM * HDIM;
    } else {
        A = g_mid + (size_t)ez * NTOK * IDIM;
        B = g_w2 + (size_t)ez * HDIM * IDIM;
    }

    uint32_t tiles = (smem_u32(dsm) + 1023u) & ~1023u;

    auto load_chunk = [&](int c, int b) {
        int kk = c * 64;
        uint32_t sA = tiles + b * STAGE;
        uint32_t sB = sA + A_BYTES;
        #pragma unroll
        for (int v = 0; v < 8; ++v) {
            int idx = v * 128 + tid;
            int r = idx >> 3, c16 = idx & 7;
            cp_async16(sA + swz_row((uint32_t)r, (uint32_t)(c16 * 16)),
                       A + (size_t)(m0 + r) * K + kk + c16 * 8);
        }
        #pragma unroll
        for (int v = 0; v < 8; ++v) {
            int idx = v * 128 + tid;
            int r = idx >> 3, c16 = idx & 7;
            cp_async16(sB + swz_row((uint32_t)r, (uint32_t)(c16 * 16)),
                       B + (size_t)(n0 + r) * K + kk + c16 * 8);
        }
        asm volatile("cp.async.commit_group;\n" ::: "memory");
    };

    auto load_part = [&](int c, int b, int p) {
        int kk = c * 64;
        uint32_t sA = tiles + b * STAGE;
        uint32_t sB = sA + A_BYTES;
        #pragma unroll
        for (int v = 0; v < 2; ++v) {
            int idx = (2 * p + v) * 128 + tid;
            int r = idx >> 3, c16 = idx & 7;
            cp_async16(sA + swz_row((uint32_t)r, (uint32_t)(c16 * 16)),
                       A + (size_t)(m0 + r) * K + kk + c16 * 8);
        }
        #pragma unroll
        for (int v = 0; v < 2; ++v) {
            int idx = (2 * p + v) * 128 + tid;
            int r = idx >> 3, c16 = idx & 7;
            cp_async16(sB + swz_row((uint32_t)r, (uint32_t)(c16 * 16)),
                       B + (size_t)(n0 + r) * K + kk + c16 * 8);
        }
    };

    const int wm = (wid & 1) * 64;
    const int wn = (wid >> 1) * 64;

    float acc[4][8][4];
    #pragma unroll
    for (int mt = 0; mt < 4; ++mt)
        #pragma unroll
        for (int nt = 0; nt < 8; ++nt)
            #pragma unroll
            for (int q = 0; q < 4; ++q) acc[mt][nt][q] = 0.f;

    const uint32_t rA = (((uint32_t)lane >> 3) & 1u) * 8u + ((uint32_t)lane & 7u);
    const uint32_t kA0 = (((uint32_t)lane >> 4) & 1u) * 16u;
    const uint32_t rB = (((uint32_t)lane >> 4) & 1u) * 8u + ((uint32_t)lane & 7u);
    const uint32_t kB0 = (((uint32_t)lane >> 3) & 1u) * 16u;

    // PDL: wait for producer kernel's data before the first dependent global read.
    cudaGridDependencySynchronize();

    load_chunk(0, 0);
    load_chunk(1, 1);

    for (int c = 0; c < NC; ++c) {
        int b = c % NSTG;
        if (c + 1 < NC) asm volatile("cp.async.wait_group 1;\n" ::: "memory");
        else            asm volatile("cp.async.wait_group 0;\n" ::: "memory");
        __syncthreads();

        const bool pf = (c + 2 < NC);
        const int pb = (c + 2) % NSTG;

        uint32_t sA = tiles + b * STAGE;
        uint32_t sB = sA + A_BYTES;

        #pragma unroll
        for (int ks = 0; ks < 4; ++ks) {
            uint32_t af[4][4];
            #pragma unroll
            for (int mt = 0; mt < 4; ++mt) {
                uint32_t row = (uint32_t)(wm + mt * 16) + rA;
                ldsm_x4(af[mt], sA + swz_row(row, (uint32_t)(ks * 32) + kA0));
            }
            uint32_t bfr[8][2];
            #pragma unroll
            for (int nt2 = 0; nt2 < 4; ++nt2) {
                uint32_t t[4];
                uint32_t row = (uint32_t)(wn + nt2 * 16) + rB;
                ldsm_x4(t, sB + swz_row(row, (uint32_t)(ks * 32) + kB0));
                bfr[2 * nt2][0] = t[0]; bfr[2 * nt2][1] = t[1];
                bfr[2 * nt2 + 1][0] = t[2]; bfr[2 * nt2 + 1][1] = t[3];
            }
            if (pf) load_part(c + 2, pb, ks);
            #pragma unroll
            for (int mt = 0; mt < 4; ++mt)
                #pragma unroll
                for (int nt = 0; nt < 8; ++nt)
                    mma16816(acc[mt][nt], af[mt], bfr[nt]);
        }
        if (pf) asm volatile("cp.async.commit_group;\n" ::: "memory");
    }

    // ------------------------- epilogue -------------------------
    const int rbase = m0 + wm + (lane >> 2);
    const int cbase = n0 + wn + (lane & 3) * 2;

    if (MODE == 0) {
        __half* mid = g_mid + (size_t)ez * NTOK * IDIM;
        #pragma unroll
        for (int mt = 0; mt < 4; ++mt) {
            #pragma unroll
            for (int half = 0; half < 2; ++half) {
                int row = rbase + mt * 16 + half * 8;
                size_t base = (size_t)row * IDIM;
                #pragma unroll
                for (int nt = 0; nt < 8; ++nt) {
                    int col = cbase + nt * 8;
                    float v0 = acc[mt][nt][half * 2 + 0];
                    float v1 = acc[mt][nt][half * 2 + 1];
                    float g0 = 0.5f * v0 * (1.0f + erff(v0 * 0.70710678118654752f));
                    float g1 = 0.5f * v1 * (1.0f + erff(v1 * 0.70710678118654752f));
                    __half2 h2;
                    h2.x = __float2half_rn(g0);
                    h2.y = __float2half_rn(g1);
                    *(__half2*)(mid + base + col) = h2;
                }
            }
        }
        __threadfence();
        cudaTriggerProgrammaticLaunchCompletion();
    } else {
        #pragma unroll
        for (int mt = 0; mt < 4; ++mt) {
            #pragma unroll
            for (int half = 0; half < 2; ++half) {
                int row = rbase + mt * 16 + half * 8;
                float pw = g_probs[row * NEXP + ez];
                size_t base = (size_t)row * HDIM;
                #pragma unroll
                for (int nt = 0; nt < 8; ++nt) {
                    int col = cbase + nt * 8;
                    float* o = outp + base + col;
                    atomicAdd(o + 0, acc[mt][nt][half * 2 + 0] * pw);
                    atomicAdd(o + 1, acc[mt][nt][half * 2 + 1] * pw);
                }
            }
        }
    }
}

// ------------------------- host launch -------------------------
extern "C" void kernel_launch(void* const* d_in, const int* in_sizes, int n_in,
                              void* d_out, int out_size) {
    const float* hs = (const float*)d_in[0];
    const float* Wr = (const float*)d_in[1];
    const float* W1 = (const float*)d_in[2];
    const float* W2 = (const float*)d_in[3];
    float* outp = (float*)d_out;

    void *xp, *w1p, *w2p, *pp;
    cudaGetSymbolAddress(&xp, g_x);
    cudaGetSymbolAddress(&w1p, g_w1);
    cudaGetSymbolAddress(&w2p, g_w2);
    cudaGetSymbolAddress(&pp, g_probs);

    const int SMEM = 1024 + 3 * 32768;   // 99328/CTA, 2 CTA/SM
    cudaFuncSetAttribute((const void*)moe_gemm<0>,
                         cudaFuncAttributeMaxDynamicSharedMemorySize, SMEM);
    cudaFuncSetAttribute((const void*)moe_gemm<1>,
                         cudaFuncAttributeMaxDynamicSharedMemorySize, SMEM);

    // Stream/event resources: created once on the first (uncaptured) correctness
    // call; only reused (as graph fork/join edges) during capture.
    static cudaStream_t s_side = nullptr;
    static cudaEvent_t ev_p1 = nullptr, ev_prep2 = nullptr;
    if (!s_side) {
        cudaStreamCreateWithFlags(&s_side, cudaStreamNonBlocking);
        cudaEventCreateWithFlags(&ev_p1, cudaEventDisableTiming);
        cudaEventCreateWithFlags(&ev_prep2, cudaEventDisableTiming);
    }

    // Main stream: minimal critical-path prep (zero-init + x, W1 conversion).
    moe_prep1_kernel<<<4096, 256>>>(hs, W1, (__half*)xp, (__half*)w1p, outp);
    cudaEventRecord(ev_p1, 0);

    // Side stream: AFTER prep1 (so it shares DRAM with tensor-bound GEMM1, not
    // with DRAM-bound prep1): router + W2 conversion.
    cudaStreamWaitEvent(s_side, ev_p1, 0);
    moe_prep2_kernel<<<4096, 256, 0, s_side>>>(hs, Wr, W2, (__half*)w2p, (float*)pp);
    cudaEventRecord(ev_prep2, s_side);

    cudaLaunchAttribute attrs[1];
    attrs[0].id = cudaLaunchAttributeProgrammaticStreamSerialization;
    attrs[0].val.programmaticStreamSerializationAllowed = 1;

    // GEMM1 (main stream): all experts; PDL overlaps prep1's tail.
    {
        cudaLaunchConfig_t cfg = {};
        cfg.gridDim = dim3(NTOK / 128, IDIM / 128, NEXP);
        cfg.blockDim = dim3(128, 1, 1);
        cfg.dynamicSmemBytes = SMEM;
        cfg.attrs = attrs;
        cfg.numAttrs = 1;
        cudaLaunchKernelEx(&cfg, moe_gemm<0>, (float*)nullptr);
    }

    // Join: GEMM2 needs probs + w2 (side stream); mid ordering via main stream.
    cudaStreamWaitEvent(0, ev_prep2, 0);

    // GEMM2: all experts, atomic accumulate into out.
    {
        cudaLaunchConfig_t cfg = {};
        cfg.gridDim = dim3(NTOK / 128, HDIM / 128, NEXP);
        cfg.blockDim = dim3(128, 1, 1);
        cfg.dynamicSmemBytes = SMEM;
        cfg.attrs = attrs;
        cfg.numAttrs = 1;
        cudaLaunchKernelEx(&cfg, moe_gemm<1>, outp);
    }
}